// round 5
// baseline (speedup 1.0000x reference)
#include <cuda_runtime.h>
#include <cuda_fp16.h>
#include <cuda_bf16.h>

#define BB 8
#define TT 4
#define NN 4096
#define FIN 3
#define UU 64
#define DOUT 3
#define EE 65536
#define EF (EE + NN)          // edges + self loops = 69632
#define BN (BB * NN)          // 32768

// ---------------- device scratch (no allocations allowed) ----------------
__device__ __half2 g_hgat2[2][BN * 32];   // hgat, half2 = (col 2p, col 2p+1), double-buffered
__device__ float   g_es[2][BN];
__device__ float   g_ed[2][BN];
__device__ int     g_cnt[NN];
__device__ int     g_cur[NN];
__device__ int     g_off[NN + 1];
__device__ int     g_srcs[EF];            // CSR: src sorted by dst

// ---------------- kernel 1: edge count + GAT step-0 node transform ----------------
// blocks [0, 4096): gat0 (h=0, so hgat = x @ W[64:67]); blocks [4096, 4096+272): count
__global__ __launch_bounds__(256) void gat0_count_kernel(
    const float* __restrict__ x, const float* __restrict__ gat_W,
    const float* __restrict__ a_src, const float* __restrict__ a_dst,
    const int* __restrict__ dst)
{
    if (blockIdx.x >= 4096) {
        int i = (blockIdx.x - 4096) * 256 + threadIdx.x;
        if (i < EF) {
            int d = (i < EE) ? dst[i] : (i - EE);
            atomicAdd(&g_cnt[d], 1);
        }
        return;
    }
    // gat0: 8 warps per block, one warp per node
    int w = threadIdx.x >> 5, lane = threadIdx.x & 31;
    int nid = blockIdx.x * 8 + w;
    int b = nid >> 12, n = nid & 4095;
    const float* xp = &x[((b * TT + 0) * NN + n) * 3];
    float x0 = __ldg(xp), x1 = __ldg(xp + 1), x2 = __ldg(xp + 2);
    int c0 = 2 * lane, c1 = 2 * lane + 1;
    float h0 = x0 * __ldg(&gat_W[64 * 64 + c0]) + x1 * __ldg(&gat_W[65 * 64 + c0])
             + x2 * __ldg(&gat_W[66 * 64 + c0]);
    float h1 = x0 * __ldg(&gat_W[64 * 64 + c1]) + x1 * __ldg(&gat_W[65 * 64 + c1])
             + x2 * __ldg(&gat_W[66 * 64 + c1]);
    g_hgat2[0][nid * 32 + lane] = __floats2half2_rn(h0, h1);
    float es = h0 * __ldg(&a_src[c0]) + h1 * __ldg(&a_src[c1]);
    float ed = h0 * __ldg(&a_dst[c0]) + h1 * __ldg(&a_dst[c1]);
    #pragma unroll
    for (int o = 16; o > 0; o >>= 1) {
        es += __shfl_down_sync(0xFFFFFFFFu, es, o);
        ed += __shfl_down_sync(0xFFFFFFFFu, ed, o);
    }
    if (lane == 0) { g_es[0][nid] = es; g_ed[0][nid] = ed; }
}

// ---------------- kernel 2: prefix scan over degree counts (+ re-zero for replay) ----
__global__ void scan_kernel() {
    __shared__ int tsum[1024];
    int tid = threadIdx.x;
    int base = tid * 4;
    int c0 = g_cnt[base + 0], c1 = g_cnt[base + 1];
    int c2 = g_cnt[base + 2], c3 = g_cnt[base + 3];
    int sum4 = c0 + c1 + c2 + c3;
    tsum[tid] = sum4;
    __syncthreads();
    for (int ofs = 1; ofs < 1024; ofs <<= 1) {
        int add = 0;
        if (tid >= ofs) add = tsum[tid - ofs];
        __syncthreads();
        tsum[tid] += add;
        __syncthreads();
    }
    int excl = tsum[tid] - sum4;
    g_off[base + 0] = excl;
    g_off[base + 1] = excl + c0;
    g_off[base + 2] = excl + c0 + c1;
    g_off[base + 3] = excl + c0 + c1 + c2;
    if (tid == 1023) g_off[NN] = tsum[1023];
    // reset counters so every graph replay sees identical state
    g_cnt[base + 0] = 0; g_cnt[base + 1] = 0; g_cnt[base + 2] = 0; g_cnt[base + 3] = 0;
    g_cur[base + 0] = 0; g_cur[base + 1] = 0; g_cur[base + 2] = 0; g_cur[base + 3] = 0;
}

// ---------------- kernel 3: CSR scatter ----------------
__global__ void scatter_kernel(const int* __restrict__ src, const int* __restrict__ dst) {
    int i = blockIdx.x * blockDim.x + threadIdx.x;
    if (i >= EF) return;
    int s, d;
    if (i < EE) { s = src[i]; d = dst[i]; }
    else        { s = i - EE; d = i - EE; }
    int pos = g_off[d] + atomicAdd(&g_cur[d], 1);
    g_srcs[pos] = s;
}

// ---------------- kernel 4: fused gather + GRU + next-step GAT (or output) ------
// 256 threads, 32 nodes/block.
//  phase 0: segment softmax+aggregate -> s (4 interleaved edge chains per warp)
//  phase 1: ru = sigmoid([x,s] @ W1 + b1)        (4-node x 4-col register tiles)
//  phase 2: c  = tanh([x, r*s] @ W2 + b2), h = u*s + (1-u)*c
//  tail:    last==0 -> hgat(t+1)/es/ed from h (2-node x 4-col tiles)
//           last==1 -> out = h @ out_W + out_b
__global__ __launch_bounds__(256) void fused_kernel(
    const float* __restrict__ x,
    const float* __restrict__ W1, const float* __restrict__ b1,
    const float* __restrict__ W2, const float* __restrict__ b2,
    const float* __restrict__ gat_W, const float* __restrict__ a_src,
    const float* __restrict__ a_dst, const float* __restrict__ gat_b,
    const float* __restrict__ oW, const float* __restrict__ ob,
    float* __restrict__ out, int t, int rd, int wr, int last)
{
    __shared__ float sW[67 * 128];    // 34.3 KB; W1 -> W2(lower) -> gat_W(lower)
    __shared__ float sz[32][68];      // [s-or-h (0..63), x (64..66)]
    __shared__ float sb1[128];
    __shared__ float sb2[64];
    __shared__ float sa[128];         // a_src | a_dst
    __shared__ float sow[192];        // out_W
    __shared__ float sob[4];
    float* srs = sW + 67 * 64;                 // r*s, aliases dead upper W1
    float* su  = sW + 67 * 64 + 32 * 64;       // u

    int tid = threadIdx.x;
    int lane = tid & 31;
    int w = tid >> 5;
    int nbase = blockIdx.x * 32;

    // kick off W1 + bias smem fills (overlaps with gather latency)
    for (int i = tid; i < 2144; i += 256)
        ((float4*)sW)[i] = ((const float4*)W1)[i];
    if (tid < 128) sb1[tid] = b1[tid];
    if (tid < 64)  sb2[tid] = b2[tid];

    // ---- phase 0: gather. warp w handles local nodes w*4 .. w*4+3 ----
    {
        int l0 = w * 4;
        float S[4], a0[4], a1[4], edv[4];
        int e[4], en[4], bofs[4];
        #pragma unroll
        for (int i = 0; i < 4; i++) {
            int nid = nbase + l0 + i;
            int n = nid & 4095;
            e[i] = g_off[n]; en[i] = g_off[n + 1];
            bofs[i] = nid - n;                    // b * NN
            edv[i] = g_ed[rd][nid];
            S[i] = 0.0f; a0[i] = 0.0f; a1[i] = 0.0f;
        }
        int mx = en[0] - e[0];
        #pragma unroll
        for (int i = 1; i < 4; i++) mx = max(mx, en[i] - e[i]);
        for (int it = 0; it < mx; it++) {
            #pragma unroll
            for (int i = 0; i < 4; i++) {
                if (e[i] < en[i]) {
                    int s = g_srcs[e[i]];
                    float ev = g_es[rd][bofs[i] + s] + edv[i];
                    ev = (ev > 0.0f) ? ev : 0.2f * ev;        // leaky_relu(0.2)
                    float wt = __expf(ev);
                    float2 f = __half22float2(g_hgat2[rd][(bofs[i] + s) * 32 + lane]);
                    S[i] += wt; a0[i] += wt * f.x; a1[i] += wt * f.y;
                    e[i]++;
                }
            }
        }
        float gb0 = __ldg(&gat_b[2 * lane]), gb1 = __ldg(&gat_b[2 * lane + 1]);
        #pragma unroll
        for (int i = 0; i < 4; i++) {
            float inv = 1.0f / S[i];
            sz[l0 + i][2 * lane]     = a0[i] * inv + gb0;
            sz[l0 + i][2 * lane + 1] = a1[i] * inv + gb1;
        }
    }
    if (tid < 96) {   // x(t)
        int ln = tid / 3, f = tid % 3;
        int nid = nbase + ln;
        int b = nid >> 12, n = nid & 4095;
        sz[ln][64 + f] = x[((b * TT + t) * NN + n) * 3 + f];
    }
    __syncthreads();

    // ---- phase 1: ru = sigmoid([x, s] @ W1 + b1)  (W1 rows: 0..2 = x, 3..66 = s) ----
    int j4 = (tid & 31) * 4;      // 0..124
    int g  = tid >> 5;            // nodes g*4 .. g*4+3
    float acc[4][4];
    #pragma unroll
    for (int i = 0; i < 4; i++)
        #pragma unroll
        for (int c = 0; c < 4; c++) acc[i][c] = sb1[j4 + c];

    #pragma unroll
    for (int f = 0; f < 3; f++) {
        float4 wv = *(float4*)&sW[f * 128 + j4];
        #pragma unroll
        for (int i = 0; i < 4; i++) {
            float z = sz[g * 4 + i][64 + f];
            acc[i][0] += z * wv.x; acc[i][1] += z * wv.y;
            acc[i][2] += z * wv.z; acc[i][3] += z * wv.w;
        }
    }
    #pragma unroll 4
    for (int k = 0; k < 64; k++) {
        float4 wv = *(float4*)&sW[(3 + k) * 128 + j4];
        #pragma unroll
        for (int i = 0; i < 4; i++) {
            float z = sz[g * 4 + i][k];
            acc[i][0] += z * wv.x; acc[i][1] += z * wv.y;
            acc[i][2] += z * wv.z; acc[i][3] += z * wv.w;
        }
    }
    __syncthreads();   // everyone done reading W1 before aliasing its buffer

    #pragma unroll
    for (int i = 0; i < 4; i++) {
        int n = g * 4 + i;
        #pragma unroll
        for (int c = 0; c < 4; c++) {
            float v = 1.0f / (1.0f + __expf(-acc[i][c]));
            if (j4 < 64) srs[n * 64 + j4 + c] = v * sz[n][j4 + c];
            else         su[n * 64 + (j4 - 64) + c] = v;
        }
    }
    for (int i = tid; i < 1072; i += 256)
        ((float4*)sW)[i] = ((const float4*)W2)[i];
    __syncthreads();

    // ---- phase 2: c = tanh([x, r*s] @ W2 + b2); h = u*s + (1-u)*c ----
    int j4b = (tid & 15) * 4;     // 0..60
    int g2  = tid >> 4;           // nodes g2*2, g2*2+1
    float a2[2][4];
    #pragma unroll
    for (int i = 0; i < 2; i++)
        #pragma unroll
        for (int c = 0; c < 4; c++) a2[i][c] = sb2[j4b + c];

    #pragma unroll
    for (int f = 0; f < 3; f++) {
        float4 wv = *(float4*)&sW[f * 64 + j4b];
        #pragma unroll
        for (int i = 0; i < 2; i++) {
            float z = sz[g2 * 2 + i][64 + f];
            a2[i][0] += z * wv.x; a2[i][1] += z * wv.y;
            a2[i][2] += z * wv.z; a2[i][3] += z * wv.w;
        }
    }
    #pragma unroll 4
    for (int k = 0; k < 64; k++) {
        float4 wv = *(float4*)&sW[(3 + k) * 64 + j4b];
        #pragma unroll
        for (int i = 0; i < 2; i++) {
            float z = srs[(g2 * 2 + i) * 64 + k];
            a2[i][0] += z * wv.x; a2[i][1] += z * wv.y;
            a2[i][2] += z * wv.z; a2[i][3] += z * wv.w;
        }
    }

    float hh[2][4];
    #pragma unroll
    for (int i = 0; i < 2; i++) {
        int n = g2 * 2 + i;
        #pragma unroll
        for (int c = 0; c < 4; c++) {
            float cc = tanhf(a2[i][c]);
            float u = su[n * 64 + j4b + c];
            float s = sz[n][j4b + c];
            hh[i][c] = u * s + (1.0f - u) * cc;
        }
    }
    __syncthreads();   // all reads of sz(s)/srs/su/sW(W2) complete

    // write h into sz[.][0..63]
    #pragma unroll
    for (int i = 0; i < 2; i++)
        #pragma unroll
        for (int c = 0; c < 4; c++) sz[g2 * 2 + i][j4b + c] = hh[i][c];

    if (!last) {
        // x(t+1) + gat_W + attention vectors
        if (tid < 96) {
            int ln = tid / 3, f = tid % 3;
            int nid = nbase + ln;
            int b = nid >> 12, n = nid & 4095;
            sz[ln][64 + f] = x[((b * TT + t + 1) * NN + n) * 3 + f];
        }
        for (int i = tid; i < 1072; i += 256)
            ((float4*)sW)[i] = ((const float4*)gat_W)[i];
        if (tid < 128) sa[tid] = (tid < 64) ? a_src[tid] : a_dst[tid - 64];
        __syncthreads();

        // gat GEMM: hgat = [h, x] @ gat_W (rows 0..63 = h, 64..66 = x == sz layout)
        int j4g = (tid & 15) * 4;
        int gg  = tid >> 4;           // nodes gg*2, gg*2+1
        float ac[2][4];
        #pragma unroll
        for (int i = 0; i < 2; i++)
            #pragma unroll
            for (int c = 0; c < 4; c++) ac[i][c] = 0.0f;

        #pragma unroll 4
        for (int k = 0; k < 67; k++) {
            float4 wv = *(float4*)&sW[k * 64 + j4g];
            #pragma unroll
            for (int i = 0; i < 2; i++) {
                float z = sz[gg * 2 + i][k];
                ac[i][0] += z * wv.x; ac[i][1] += z * wv.y;
                ac[i][2] += z * wv.z; ac[i][3] += z * wv.w;
            }
        }
        #pragma unroll
        for (int i = 0; i < 2; i++) {
            int nid = nbase + gg * 2 + i;
            int p = j4g >> 1;
            g_hgat2[wr][nid * 32 + p]     = __floats2half2_rn(ac[i][0], ac[i][1]);
            g_hgat2[wr][nid * 32 + p + 1] = __floats2half2_rn(ac[i][2], ac[i][3]);

            float v1 = ac[i][0] * sa[j4g]     + ac[i][1] * sa[j4g + 1]
                     + ac[i][2] * sa[j4g + 2] + ac[i][3] * sa[j4g + 3];
            float v2 = ac[i][0] * sa[64 + j4g]     + ac[i][1] * sa[64 + j4g + 1]
                     + ac[i][2] * sa[64 + j4g + 2] + ac[i][3] * sa[64 + j4g + 3];
            #pragma unroll
            for (int o = 8; o > 0; o >>= 1) {
                v1 += __shfl_down_sync(0xFFFFFFFFu, v1, o, 16);
                v2 += __shfl_down_sync(0xFFFFFFFFu, v2, o, 16);
            }
            if ((tid & 15) == 0) { g_es[wr][nid] = v1; g_ed[wr][nid] = v2; }
        }
    } else {
        // output projection: out = h @ out_W + out_b
        if (tid < 192) sow[tid] = oW[tid];
        if (tid < 3)   sob[tid] = ob[tid];
        __syncthreads();
        if (tid < 96) {
            int ln = tid / 3, d = tid % 3;
            float acc3 = sob[d];
            #pragma unroll 8
            for (int k = 0; k < 64; k++) acc3 += sz[ln][k] * sow[k * 3 + d];
            out[(nbase + ln) * 3 + d] = acc3;
        }
    }
}

// ---------------- launch ----------------
extern "C" void kernel_launch(void* const* d_in, const int* in_sizes, int n_in,
                              void* d_out, int out_size)
{
    const float* x       = (const float*)d_in[0];
    const int*   src     = (const int*)  d_in[1];
    const int*   dst     = (const int*)  d_in[2];
    const float* gat_W   = (const float*)d_in[3];
    const float* a_src   = (const float*)d_in[4];
    const float* a_dst   = (const float*)d_in[5];
    const float* gat_b   = (const float*)d_in[6];
    const float* gru1_W  = (const float*)d_in[7];
    const float* gru1_b  = (const float*)d_in[8];
    const float* gru2_W  = (const float*)d_in[9];
    const float* gru2_b  = (const float*)d_in[10];
    const float* out_W   = (const float*)d_in[11];
    const float* out_b   = (const float*)d_in[12];
    float* out = (float*)d_out;

    // CSR build + step-0 GAT node transform (merged where independent)
    gat0_count_kernel<<<4096 + 272, 256>>>(x, gat_W, a_src, a_dst, dst);
    scan_kernel<<<1, 1024>>>();
    scatter_kernel<<<(EF + 255) / 256, 256>>>(src, dst);

    for (int t = 0; t < TT; t++) {
        int rd = t & 1, wr = 1 - (t & 1);
        fused_kernel<<<BN / 32, 256>>>(x, gru1_W, gru1_b, gru2_W, gru2_b,
                                       gat_W, a_src, a_dst, gat_b,
                                       out_W, out_b, out,
                                       t, rd, wr, (t == TT - 1) ? 1 : 0);
    }
}

// round 6
// speedup vs baseline: 1.2434x; 1.2434x over previous
#include <cuda_runtime.h>
#include <cuda_fp16.h>
#include <cuda_bf16.h>

typedef unsigned long long ull;

#define BB 8
#define TT 4
#define NN 4096
#define EE 65536
#define EF (EE + NN)          // edges + self loops = 69632
#define BN (BB * NN)          // 32768

// ---------------- device scratch ----------------
__device__ __half2 g_hgat2[BN * 32];   // hgat, half2 = (col 2p, col 2p+1)
__device__ float   g_es[BN];
__device__ float   g_ed[BN];
__device__ float   g_s[BN * 64];       // GAT output (fp32, feeds GRU)
__device__ int     g_cnt[NN];
__device__ int     g_cur[NN];
__device__ int     g_off[NN + 1];
__device__ int     g_srcs[EF];

// ---------------- f32x2 helpers ----------------
__device__ __forceinline__ ull pack2(float a, float b) {
    ull r; asm("mov.b64 %0, {%1, %2};" : "=l"(r) : "f"(a), "f"(b)); return r;
}
__device__ __forceinline__ void unpack2(ull v, float& a, float& b) {
    asm("mov.b64 {%0, %1}, %2;" : "=f"(a), "=f"(b) : "l"(v));
}
__device__ __forceinline__ ull fma2(ull a, ull b, ull c) {
    ull d; asm("fma.rn.f32x2 %0, %1, %2, %3;" : "=l"(d) : "l"(a), "l"(b), "l"(c));
    return d;
}

// ---------------- kernel 1: edge count + GAT step-0 node transform ----------------
__global__ __launch_bounds__(256) void gat0_count_kernel(
    const float* __restrict__ x, const float* __restrict__ gat_W,
    const float* __restrict__ a_src, const float* __restrict__ a_dst,
    const int* __restrict__ dst)
{
    if (blockIdx.x >= 4096) {
        int i = (blockIdx.x - 4096) * 256 + threadIdx.x;
        if (i < EF) {
            int d = (i < EE) ? dst[i] : (i - EE);
            atomicAdd(&g_cnt[d], 1);
        }
        return;
    }
    int w = threadIdx.x >> 5, lane = threadIdx.x & 31;
    int nid = blockIdx.x * 8 + w;
    int b = nid >> 12, n = nid & 4095;
    const float* xp = &x[((b * TT + 0) * NN + n) * 3];
    float x0 = __ldg(xp), x1 = __ldg(xp + 1), x2 = __ldg(xp + 2);
    int c0 = 2 * lane, c1 = 2 * lane + 1;
    float h0 = x0 * __ldg(&gat_W[64 * 64 + c0]) + x1 * __ldg(&gat_W[65 * 64 + c0])
             + x2 * __ldg(&gat_W[66 * 64 + c0]);
    float h1 = x0 * __ldg(&gat_W[64 * 64 + c1]) + x1 * __ldg(&gat_W[65 * 64 + c1])
             + x2 * __ldg(&gat_W[66 * 64 + c1]);
    g_hgat2[nid * 32 + lane] = __floats2half2_rn(h0, h1);
    float es = h0 * __ldg(&a_src[c0]) + h1 * __ldg(&a_src[c1]);
    float ed = h0 * __ldg(&a_dst[c0]) + h1 * __ldg(&a_dst[c1]);
    #pragma unroll
    for (int o = 16; o > 0; o >>= 1) {
        es += __shfl_down_sync(0xFFFFFFFFu, es, o);
        ed += __shfl_down_sync(0xFFFFFFFFu, ed, o);
    }
    if (lane == 0) { g_es[nid] = es; g_ed[nid] = ed; }
}

// ---------------- kernel 2: prefix scan (+ re-zero counters for graph replay) ----
__global__ void scan_kernel() {
    __shared__ int tsum[1024];
    int tid = threadIdx.x;
    int base = tid * 4;
    int c0 = g_cnt[base + 0], c1 = g_cnt[base + 1];
    int c2 = g_cnt[base + 2], c3 = g_cnt[base + 3];
    int sum4 = c0 + c1 + c2 + c3;
    tsum[tid] = sum4;
    __syncthreads();
    for (int ofs = 1; ofs < 1024; ofs <<= 1) {
        int add = 0;
        if (tid >= ofs) add = tsum[tid - ofs];
        __syncthreads();
        tsum[tid] += add;
        __syncthreads();
    }
    int excl = tsum[tid] - sum4;
    g_off[base + 0] = excl;
    g_off[base + 1] = excl + c0;
    g_off[base + 2] = excl + c0 + c1;
    g_off[base + 3] = excl + c0 + c1 + c2;
    if (tid == 1023) g_off[NN] = tsum[1023];
    g_cnt[base + 0] = 0; g_cnt[base + 1] = 0; g_cnt[base + 2] = 0; g_cnt[base + 3] = 0;
    g_cur[base + 0] = 0; g_cur[base + 1] = 0; g_cur[base + 2] = 0; g_cur[base + 3] = 0;
}

// ---------------- kernel 3: CSR scatter ----------------
__global__ void scatter_kernel(const int* __restrict__ src, const int* __restrict__ dst) {
    int i = blockIdx.x * blockDim.x + threadIdx.x;
    if (i >= EF) return;
    int s, d;
    if (i < EE) { s = src[i]; d = dst[i]; }
    else        { s = i - EE; d = i - EE; }
    int pos = g_off[d] + atomicAdd(&g_cur[d], 1);
    g_srcs[pos] = s;
}

// ---------------- kernel 4: gather (standalone, latency-tolerant) ----------------
// one warp per (b, dst); lane covers cols (2*lane, 2*lane+1)
__global__ __launch_bounds__(256) void gat_gather_kernel(const float* __restrict__ gat_b)
{
    int gw = blockIdx.x * 8 + (threadIdx.x >> 5);
    int lane = threadIdx.x & 31;
    int b = gw >> 12, n = gw & 4095;
    int bofs = b * NN;
    float edv = g_ed[bofs + n];
    int e = g_off[n], en = g_off[n + 1];
    float S = 0.0f, a0 = 0.0f, a1 = 0.0f;
    for (; e < en; e++) {
        int s = g_srcs[e];
        float ev = g_es[bofs + s] + edv;
        ev = (ev > 0.0f) ? ev : 0.2f * ev;      // leaky_relu(0.2)
        float w = __expf(ev);
        float2 f = __half22float2(g_hgat2[(bofs + s) * 32 + lane]);
        S += w; a0 += w * f.x; a1 += w * f.y;
    }
    float inv = 1.0f / S;
    float gb0 = __ldg(&gat_b[2 * lane]), gb1 = __ldg(&gat_b[2 * lane + 1]);
    ((float2*)(g_s + gw * 64))[lane] = make_float2(a0 * inv + gb0, a1 * inv + gb1);
}

// ---------------- kernel 5: fused GRU + next-step GAT node transform -------------
// 256 threads, 32 nodes/block. Dynamic smem layout (bytes):
//   [0, 34304)      sW   : float[67*128]  (W1 -> lower 67*64 for W2 -> gat_W)
//   [17152, 33536)  srs2 : ull[32*64]     (r*s duplicated; aliases dead W1 upper)
//   [34304, 51712)  sz2  : ull[32*68]     ((v,v) pairs: s/h in 0..63, x in 64..66)
//   [51712, 59904)  su   : float[32*64]
//   [59904..]       sb1[128], sb2[64], sa[128], sow[192], sob[4]
#define SM_TOTAL 61968
extern __shared__ char dynsm[];
__global__ __launch_bounds__(256) void gru_gat_kernel(
    const float* __restrict__ x,
    const float* __restrict__ W1, const float* __restrict__ b1,
    const float* __restrict__ W2, const float* __restrict__ b2,
    const float* __restrict__ gat_W, const float* __restrict__ a_src,
    const float* __restrict__ a_dst,
    const float* __restrict__ oW, const float* __restrict__ ob,
    float* __restrict__ out, int t, int last)
{
    float* sW   = (float*)dynsm;
    ull*   srs2 = (ull*)(dynsm + 17152);
    ull*   sz2  = (ull*)(dynsm + 34304);
    float* su   = (float*)(dynsm + 51712);
    float* sb1  = (float*)(dynsm + 59904);
    float* sb2  = (float*)(dynsm + 60416);
    float* sa   = (float*)(dynsm + 60672);
    float* sow  = (float*)(dynsm + 61184);
    float* sob  = (float*)(dynsm + 61952);

    int tid = threadIdx.x;
    int nbase = blockIdx.x * 32;

    // fill W1 + biases
    for (int i = tid; i < 2144; i += 256)
        ((float4*)sW)[i] = ((const float4*)W1)[i];
    if (tid < 128) sb1[tid] = b1[tid];
    if (tid < 64)  sb2[tid] = b2[tid];

    // s (duplicated pairs) : sz2[n*68 + k] = (s_k, s_k)
    for (int i = tid; i < 2048; i += 256) {
        int ln = i >> 6, k = i & 63;
        float v = g_s[(nbase + ln) * 64 + k];
        sz2[ln * 68 + k] = pack2(v, v);
    }
    if (tid < 96) {   // x(t)
        int ln = tid / 3, f = tid % 3;
        int nid = nbase + ln;
        int b = nid >> 12, n = nid & 4095;
        float v = x[((b * TT + t) * NN + n) * 3 + f];
        sz2[ln * 68 + 64 + f] = pack2(v, v);
    }
    __syncthreads();

    // ---- phase 1: ru = sigmoid([x, s] @ W1 + b1) ; 4-node x 4-col tiles ----
    int j4 = (tid & 31) * 4;      // 0..124
    int g  = tid >> 5;            // nodes g*4 .. g*4+3
    ull acc01[4], acc23[4];
    {
        ull i01 = pack2(sb1[j4], sb1[j4 + 1]);
        ull i23 = pack2(sb1[j4 + 2], sb1[j4 + 3]);
        #pragma unroll
        for (int i = 0; i < 4; i++) { acc01[i] = i01; acc23[i] = i23; }
    }
    #pragma unroll
    for (int f = 0; f < 3; f++) {
        ull w01 = *(ull*)&sW[f * 128 + j4];
        ull w23 = *(ull*)&sW[f * 128 + j4 + 2];
        #pragma unroll
        for (int i = 0; i < 4; i++) {
            ull z = sz2[(g * 4 + i) * 68 + 64 + f];
            acc01[i] = fma2(z, w01, acc01[i]);
            acc23[i] = fma2(z, w23, acc23[i]);
        }
    }
    #pragma unroll 4
    for (int k = 0; k < 64; k++) {
        ull w01 = *(ull*)&sW[(3 + k) * 128 + j4];
        ull w23 = *(ull*)&sW[(3 + k) * 128 + j4 + 2];
        #pragma unroll
        for (int i = 0; i < 4; i++) {
            ull z = sz2[(g * 4 + i) * 68 + k];
            acc01[i] = fma2(z, w01, acc01[i]);
            acc23[i] = fma2(z, w23, acc23[i]);
        }
    }
    __syncthreads();   // all W1 reads done before aliasing upper half (srs2)

    #pragma unroll
    for (int i = 0; i < 4; i++) {
        int n = g * 4 + i;
        float v[4];
        unpack2(acc01[i], v[0], v[1]);
        unpack2(acc23[i], v[2], v[3]);
        #pragma unroll
        for (int c = 0; c < 4; c++) {
            float sg = 1.0f / (1.0f + __expf(-v[c]));
            if (j4 < 64) {
                float s = ((float2*)&sz2[n * 68 + j4 + c])->x;
                float rs = sg * s;
                srs2[n * 64 + j4 + c] = pack2(rs, rs);
            } else {
                su[n * 64 + (j4 - 64) + c] = sg;
            }
        }
    }
    for (int i = tid; i < 1072; i += 256)
        ((float4*)sW)[i] = ((const float4*)W2)[i];
    __syncthreads();

    // ---- phase 2: c = tanh([x, r*s] @ W2 + b2); h = u*s + (1-u)*c ----
    int j4b = (tid & 15) * 4;     // 0..60
    int g2  = tid >> 4;           // nodes g2*2, g2*2+1
    ull b01 = pack2(sb2[j4b], sb2[j4b + 1]);
    ull b23 = pack2(sb2[j4b + 2], sb2[j4b + 3]);
    ull a01[2] = {b01, b01}, a23[2] = {b23, b23};
    #pragma unroll
    for (int f = 0; f < 3; f++) {
        ull w01 = *(ull*)&sW[f * 64 + j4b];
        ull w23 = *(ull*)&sW[f * 64 + j4b + 2];
        #pragma unroll
        for (int i = 0; i < 2; i++) {
            ull z = sz2[(g2 * 2 + i) * 68 + 64 + f];
            a01[i] = fma2(z, w01, a01[i]);
            a23[i] = fma2(z, w23, a23[i]);
        }
    }
    #pragma unroll 4
    for (int k = 0; k < 64; k++) {
        ull w01 = *(ull*)&sW[(3 + k) * 64 + j4b];
        ull w23 = *(ull*)&sW[(3 + k) * 64 + j4b + 2];
        #pragma unroll
        for (int i = 0; i < 2; i++) {
            ull z = srs2[(g2 * 2 + i) * 64 + k];
            a01[i] = fma2(z, w01, a01[i]);
            a23[i] = fma2(z, w23, a23[i]);
        }
    }
    float hh[2][4];
    #pragma unroll
    for (int i = 0; i < 2; i++) {
        int n = g2 * 2 + i;
        float v[4];
        unpack2(a01[i], v[0], v[1]);
        unpack2(a23[i], v[2], v[3]);
        #pragma unroll
        for (int c = 0; c < 4; c++) {
            float cc = tanhf(v[c]);
            float u = su[n * 64 + j4b + c];
            float s = ((float2*)&sz2[n * 68 + j4b + c])->x;
            hh[i][c] = u * s + (1.0f - u) * cc;
        }
    }
    __syncthreads();   // all reads of sz2(s)/srs2/su/W2 done

    // write h (duplicated) into sz2[.][0..63]
    #pragma unroll
    for (int i = 0; i < 2; i++)
        #pragma unroll
        for (int c = 0; c < 4; c++)
            sz2[(g2 * 2 + i) * 68 + j4b + c] = pack2(hh[i][c], hh[i][c]);

    if (!last) {
        if (tid < 96) {   // x(t+1)
            int ln = tid / 3, f = tid % 3;
            int nid = nbase + ln;
            int b = nid >> 12, n = nid & 4095;
            float v = x[((b * TT + t + 1) * NN + n) * 3 + f];
            sz2[ln * 68 + 64 + f] = pack2(v, v);
        }
        for (int i = tid; i < 1072; i += 256)
            ((float4*)sW)[i] = ((const float4*)gat_W)[i];
        if (tid < 128) sa[tid] = (tid < 64) ? a_src[tid] : a_dst[tid - 64];
        __syncthreads();

        // hgat = [h, x] @ gat_W ; rows 0..66 == sz2 layout exactly
        int j4g = (tid & 15) * 4;
        int gg  = tid >> 4;
        ull c01[2] = {0ull, 0ull}, c23[2] = {0ull, 0ull};
        #pragma unroll 4
        for (int k = 0; k < 67; k++) {
            ull w01 = *(ull*)&sW[k * 64 + j4g];
            ull w23 = *(ull*)&sW[k * 64 + j4g + 2];
            #pragma unroll
            for (int i = 0; i < 2; i++) {
                ull z = sz2[(gg * 2 + i) * 68 + k];
                c01[i] = fma2(z, w01, c01[i]);
                c23[i] = fma2(z, w23, c23[i]);
            }
        }
        #pragma unroll
        for (int i = 0; i < 2; i++) {
            int nid = nbase + gg * 2 + i;
            float v[4];
            unpack2(c01[i], v[0], v[1]);
            unpack2(c23[i], v[2], v[3]);
            int p = j4g >> 1;
            g_hgat2[nid * 32 + p]     = __floats2half2_rn(v[0], v[1]);
            g_hgat2[nid * 32 + p + 1] = __floats2half2_rn(v[2], v[3]);
            float v1 = v[0] * sa[j4g]     + v[1] * sa[j4g + 1]
                     + v[2] * sa[j4g + 2] + v[3] * sa[j4g + 3];
            float v2 = v[0] * sa[64 + j4g]     + v[1] * sa[64 + j4g + 1]
                     + v[2] * sa[64 + j4g + 2] + v[3] * sa[64 + j4g + 3];
            #pragma unroll
            for (int o = 8; o > 0; o >>= 1) {
                v1 += __shfl_down_sync(0xFFFFFFFFu, v1, o, 16);
                v2 += __shfl_down_sync(0xFFFFFFFFu, v2, o, 16);
            }
            if ((tid & 15) == 0) { g_es[nid] = v1; g_ed[nid] = v2; }
        }
    } else {
        // out = h @ out_W + out_b
        if (tid < 192) sow[tid] = oW[tid];
        if (tid < 3)   sob[tid] = ob[tid];
        __syncthreads();
        if (tid < 96) {
            int ln = tid / 3, d = tid % 3;
            float acc3 = sob[d];
            #pragma unroll 8
            for (int k = 0; k < 64; k++)
                acc3 += ((float2*)&sz2[ln * 68 + k])->x * sow[k * 3 + d];
            out[(nbase + ln) * 3 + d] = acc3;
        }
    }
}

// ---------------- launch ----------------
extern "C" void kernel_launch(void* const* d_in, const int* in_sizes, int n_in,
                              void* d_out, int out_size)
{
    const float* x       = (const float*)d_in[0];
    const int*   src     = (const int*)  d_in[1];
    const int*   dst     = (const int*)  d_in[2];
    const float* gat_W   = (const float*)d_in[3];
    const float* a_src   = (const float*)d_in[4];
    const float* a_dst   = (const float*)d_in[5];
    const float* gat_b   = (const float*)d_in[6];
    const float* gru1_W  = (const float*)d_in[7];
    const float* gru1_b  = (const float*)d_in[8];
    const float* gru2_W  = (const float*)d_in[9];
    const float* gru2_b  = (const float*)d_in[10];
    const float* out_W   = (const float*)d_in[11];
    const float* out_b   = (const float*)d_in[12];
    float* out = (float*)d_out;

    cudaFuncSetAttribute(gru_gat_kernel,
                         cudaFuncAttributeMaxDynamicSharedMemorySize, 65536);

    gat0_count_kernel<<<4096 + 272, 256>>>(x, gat_W, a_src, a_dst, dst);
    scan_kernel<<<1, 1024>>>();
    scatter_kernel<<<(EF + 255) / 256, 256>>>(src, dst);

    for (int t = 0; t < TT; t++) {
        gat_gather_kernel<<<BN / 8, 256>>>(gat_b);
        gru_gat_kernel<<<BN / 32, 256, SM_TOTAL>>>(
            x, gru1_W, gru1_b, gru2_W, gru2_b,
            gat_W, a_src, a_dst, out_W, out_b, out,
            t, (t == TT - 1) ? 1 : 0);
    }
}

// round 10
// speedup vs baseline: 1.5267x; 1.2278x over previous
#include <cuda_runtime.h>
#include <cuda_fp16.h>
#include <cuda_bf16.h>

#define BB 8
#define TT 4
#define NN 4096
#define EE 65536
#define EF (EE + NN)          // edges + self loops = 69632
#define BN (BB * NN)          // 32768

// ---------------- device scratch ----------------
__device__ __half2 g_hgat2[NN * BB * 32];  // [(n*8+b)*32 + lane] = cols (2l, 2l+1)
__device__ float   g_est[NN * BB];         // es, transposed [n*8 + b]
__device__ float   g_edt[NN * BB];         // ed, transposed [n*8 + b]
__device__ float   g_s[BN * 64];           // GAT output, [b*NN+n][64]
__device__ float   g_h[BN * 64];           // GRU hidden state
__device__ int     g_cnt[NN];
__device__ int     g_cur[NN];
__device__ int     g_off[NN + 1];
__device__ int     g_srcs[EF];

// ---------------- kernel 1: edge count + GAT step-0 node transform ----------------
// h=0 at t=0, so hgat = x @ W[64:67]
__global__ __launch_bounds__(256) void gat0_count_kernel(
    const float* __restrict__ x, const float* __restrict__ gat_W,
    const float* __restrict__ a_src, const float* __restrict__ a_dst,
    const int* __restrict__ dst)
{
    if (blockIdx.x >= 4096) {
        int i = (blockIdx.x - 4096) * 256 + threadIdx.x;
        if (i < EF) {
            int d = (i < EE) ? dst[i] : (i - EE);
            atomicAdd(&g_cnt[d], 1);
        }
        return;
    }
    int w = threadIdx.x >> 5, lane = threadIdx.x & 31;
    int nid = blockIdx.x * 8 + w;
    int b = nid >> 12, n = nid & 4095;
    const float* xp = &x[((b * TT + 0) * NN + n) * 3];
    float x0 = __ldg(xp), x1 = __ldg(xp + 1), x2 = __ldg(xp + 2);
    int c0 = 2 * lane, c1 = 2 * lane + 1;
    float h0 = x0 * __ldg(&gat_W[64 * 64 + c0]) + x1 * __ldg(&gat_W[65 * 64 + c0])
             + x2 * __ldg(&gat_W[66 * 64 + c0]);
    float h1 = x0 * __ldg(&gat_W[64 * 64 + c1]) + x1 * __ldg(&gat_W[65 * 64 + c1])
             + x2 * __ldg(&gat_W[66 * 64 + c1]);
    g_hgat2[(n * 8 + b) * 32 + lane] = __floats2half2_rn(h0, h1);
    float es = h0 * __ldg(&a_src[c0]) + h1 * __ldg(&a_src[c1]);
    float ed = h0 * __ldg(&a_dst[c0]) + h1 * __ldg(&a_dst[c1]);
    #pragma unroll
    for (int o = 16; o > 0; o >>= 1) {
        es += __shfl_down_sync(0xFFFFFFFFu, es, o);
        ed += __shfl_down_sync(0xFFFFFFFFu, ed, o);
    }
    if (lane == 0) { g_est[n * 8 + b] = es; g_edt[n * 8 + b] = ed; }
}

// ---------------- kernel 2: prefix scan (+ re-zero counters for graph replay) ----
__global__ void scan_kernel() {
    __shared__ int tsum[1024];
    int tid = threadIdx.x;
    int base = tid * 4;
    int c0 = g_cnt[base + 0], c1 = g_cnt[base + 1];
    int c2 = g_cnt[base + 2], c3 = g_cnt[base + 3];
    int sum4 = c0 + c1 + c2 + c3;
    tsum[tid] = sum4;
    __syncthreads();
    for (int ofs = 1; ofs < 1024; ofs <<= 1) {
        int add = 0;
        if (tid >= ofs) add = tsum[tid - ofs];
        __syncthreads();
        tsum[tid] += add;
        __syncthreads();
    }
    int excl = tsum[tid] - sum4;
    g_off[base + 0] = excl;
    g_off[base + 1] = excl + c0;
    g_off[base + 2] = excl + c0 + c1;
    g_off[base + 3] = excl + c0 + c1 + c2;
    if (tid == 1023) g_off[NN] = tsum[1023];
    g_cnt[base + 0] = 0; g_cnt[base + 1] = 0; g_cnt[base + 2] = 0; g_cnt[base + 3] = 0;
    g_cur[base + 0] = 0; g_cur[base + 1] = 0; g_cur[base + 2] = 0; g_cur[base + 3] = 0;
}

// ---------------- kernel 3: CSR scatter ----------------
__global__ void scatter_kernel(const int* __restrict__ src, const int* __restrict__ dst) {
    int i = blockIdx.x * blockDim.x + threadIdx.x;
    if (i >= EF) return;
    int s, d;
    if (i < EE) { s = src[i]; d = dst[i]; }
    else        { s = i - EE; d = i - EE; }
    int pos = g_off[d] + atomicAdd(&g_cur[d], 1);
    g_srcs[pos] = s;
}

// ---------------- kernel 4: gather, all 8 batches per warp ----------------
// one warp per dst node n; lane covers cols (2*lane, 2*lane+1)
__global__ __launch_bounds__(256) void gat_gather_kernel(const float* __restrict__ gat_b)
{
    int n = blockIdx.x * 8 + (threadIdx.x >> 5);
    int lane = threadIdx.x & 31;

    float edv[8];
    {
        float4 e01 = *(const float4*)&g_edt[n * 8];
        float4 e23 = *(const float4*)&g_edt[n * 8 + 4];
        edv[0] = e01.x; edv[1] = e01.y; edv[2] = e01.z; edv[3] = e01.w;
        edv[4] = e23.x; edv[5] = e23.y; edv[6] = e23.z; edv[7] = e23.w;
    }
    float S[8], a0[8], a1[8];
    #pragma unroll
    for (int b = 0; b < 8; b++) { S[b] = 0.0f; a0[b] = 0.0f; a1[b] = 0.0f; }

    int e = g_off[n], en = g_off[n + 1];
    for (; e < en; e++) {
        int s = __ldg(&g_srcs[e]);
        float4 s01 = *(const float4*)&g_est[s * 8];
        float4 s23 = *(const float4*)&g_est[s * 8 + 4];
        float esv[8] = {s01.x, s01.y, s01.z, s01.w, s23.x, s23.y, s23.z, s23.w};
        const __half2* hp = &g_hgat2[s * 8 * 32 + lane];
        #pragma unroll
        for (int b = 0; b < 8; b++) {
            float ev = esv[b] + edv[b];
            ev = fmaxf(ev, 0.2f * ev);            // leaky_relu(0.2)
            float w = __expf(ev);
            float2 f = __half22float2(hp[b * 32]);
            S[b] += w; a0[b] += w * f.x; a1[b] += w * f.y;
        }
    }
    float gb0 = __ldg(&gat_b[2 * lane]), gb1 = __ldg(&gat_b[2 * lane + 1]);
    #pragma unroll
    for (int b = 0; b < 8; b++) {
        float inv = 1.0f / S[b];
        ((float2*)(g_s + (b * NN + n) * 64))[lane] =
            make_float2(a0[b] * inv + gb0, a1[b] * inv + gb1);
    }
}

// ---------------- kernel 5: GAT node transform (steps 1..3) ----------------
// 256 threads, 64 nodes/block. 4-node x 4-col register tiles. Reads g_h + x(t).
__global__ __launch_bounds__(256) void gat_node_kernel(
    const float* __restrict__ x, const float* __restrict__ gat_W,
    const float* __restrict__ a_src, const float* __restrict__ a_dst, int t)
{
    __shared__ float sW[67 * 64];
    __shared__ float sz[64][68];
    __shared__ float sa[128];

    int tid = threadIdx.x;
    for (int i = tid; i < 1072; i += 256)
        ((float4*)sW)[i] = ((const float4*)gat_W)[i];
    if (tid < 128) sa[tid] = (tid < 64) ? a_src[tid] : a_dst[tid - 64];

    int nbase = blockIdx.x * 64;
    for (int i = tid; i < 1024; i += 256) {
        int ln = i >> 4, kq = i & 15;
        float4 v = ((const float4*)g_h)[(nbase + ln) * 16 + kq];
        sz[ln][kq * 4 + 0] = v.x; sz[ln][kq * 4 + 1] = v.y;
        sz[ln][kq * 4 + 2] = v.z; sz[ln][kq * 4 + 3] = v.w;
    }
    if (tid < 192) {
        int ln = tid / 3, f = tid % 3;
        int nid = nbase + ln;
        int b = nid >> 12, n = nid & 4095;
        sz[ln][64 + f] = x[((b * TT + t) * NN + n) * 3 + f];
    }
    __syncthreads();

    int j4 = (tid & 15) * 4;
    int g  = tid >> 4;
    float acc[4][4];
    #pragma unroll
    for (int i = 0; i < 4; i++)
        #pragma unroll
        for (int c = 0; c < 4; c++) acc[i][c] = 0.0f;

    #pragma unroll 4
    for (int k = 0; k < 67; k++) {
        float4 w = *(float4*)&sW[k * 64 + j4];
        #pragma unroll
        for (int i = 0; i < 4; i++) {
            float z = sz[g * 4 + i][k];
            acc[i][0] += z * w.x; acc[i][1] += z * w.y;
            acc[i][2] += z * w.z; acc[i][3] += z * w.w;
        }
    }

    #pragma unroll
    for (int i = 0; i < 4; i++) {
        int nid = nbase + g * 4 + i;
        int b = nid >> 12, n = nid & 4095;
        int p = j4 >> 1;
        g_hgat2[(n * 8 + b) * 32 + p]     = __floats2half2_rn(acc[i][0], acc[i][1]);
        g_hgat2[(n * 8 + b) * 32 + p + 1] = __floats2half2_rn(acc[i][2], acc[i][3]);

        float v1 = acc[i][0] * sa[j4]      + acc[i][1] * sa[j4 + 1]
                 + acc[i][2] * sa[j4 + 2]  + acc[i][3] * sa[j4 + 3];
        float v2 = acc[i][0] * sa[64 + j4]     + acc[i][1] * sa[64 + j4 + 1]
                 + acc[i][2] * sa[64 + j4 + 2] + acc[i][3] * sa[64 + j4 + 3];
        #pragma unroll
        for (int o2 = 8; o2 > 0; o2 >>= 1) {
            v1 += __shfl_down_sync(0xFFFFFFFFu, v1, o2, 16);
            v2 += __shfl_down_sync(0xFFFFFFFFu, v2, o2, 16);
        }
        if ((tid & 15) == 0) { g_est[n * 8 + b] = v1; g_edt[n * 8 + b] = v2; }
    }
}

// ---------------- kernel 6: GRU cell (+ fused output projection on last step) ----
// 256 threads, 32 nodes/block (round-4 structure).
__global__ __launch_bounds__(256) void gru_kernel(
    const float* __restrict__ x,
    const float* __restrict__ W1, const float* __restrict__ b1,
    const float* __restrict__ W2, const float* __restrict__ b2,
    const float* __restrict__ oW, const float* __restrict__ ob,
    float* __restrict__ out, int t, int last)
{
    __shared__ float sW[67 * 128];    // 34.3 KB, phase2 reuses lower 67*64
    __shared__ float sz[32][68];      // [s (0..63), x (64..66)]
    __shared__ float sb1[128];
    __shared__ float sb2[64];
    __shared__ float sow[192];
    __shared__ float sob[4];
    float* srs = sW + 67 * 64;                 // r*s, aliases dead upper W1
    float* su  = sW + 67 * 64 + 32 * 64;       // u

    int tid = threadIdx.x;
    int nbase = blockIdx.x * 32;

    for (int i = tid; i < 2144; i += 256)
        ((float4*)sW)[i] = ((const float4*)W1)[i];
    if (tid < 128) sb1[tid] = b1[tid];
    if (tid < 64)  sb2[tid] = b2[tid];
    if (last) {
        if (tid < 192) sow[tid] = oW[tid];
        if (tid < 3)   sob[tid] = ob[tid];
    }

    for (int i = tid; i < 512; i += 256) {
        int ln = i >> 4, kq = (i & 15) * 4;
        float4 v = ((const float4*)g_s)[(nbase + ln) * 16 + (i & 15)];
        sz[ln][kq + 0] = v.x; sz[ln][kq + 1] = v.y;
        sz[ln][kq + 2] = v.z; sz[ln][kq + 3] = v.w;
    }
    if (tid < 96) {
        int ln = tid / 3, f = tid % 3;
        int nid = nbase + ln;
        int b = nid >> 12, n = nid & 4095;
        sz[ln][64 + f] = x[((b * TT + t) * NN + n) * 3 + f];
    }
    __syncthreads();

    // ---- phase 1: ru = sigmoid([x, s] @ W1 + b1) ----  (W1 rows: 0..2 x, 3..66 s)
    int j4 = (tid & 31) * 4;
    int g  = tid >> 5;
    float acc[4][4];
    #pragma unroll
    for (int i = 0; i < 4; i++)
        #pragma unroll
        for (int c = 0; c < 4; c++) acc[i][c] = sb1[j4 + c];

    #pragma unroll
    for (int f = 0; f < 3; f++) {
        float4 wv = *(float4*)&sW[f * 128 + j4];
        #pragma unroll
        for (int i = 0; i < 4; i++) {
            float z = sz[g * 4 + i][64 + f];
            acc[i][0] += z * wv.x; acc[i][1] += z * wv.y;
            acc[i][2] += z * wv.z; acc[i][3] += z * wv.w;
        }
    }
    #pragma unroll 4
    for (int k = 0; k < 64; k++) {
        float4 wv = *(float4*)&sW[(3 + k) * 128 + j4];
        #pragma unroll
        for (int i = 0; i < 4; i++) {
            float z = sz[g * 4 + i][k];
            acc[i][0] += z * wv.x; acc[i][1] += z * wv.y;
            acc[i][2] += z * wv.z; acc[i][3] += z * wv.w;
        }
    }
    __syncthreads();

    #pragma unroll
    for (int i = 0; i < 4; i++) {
        int n = g * 4 + i;
        #pragma unroll
        for (int c = 0; c < 4; c++) {
            float v = 1.0f / (1.0f + __expf(-acc[i][c]));
            if (j4 < 64) srs[n * 64 + j4 + c] = v * sz[n][j4 + c];
            else         su[n * 64 + (j4 - 64) + c] = v;
        }
    }
    for (int i = tid; i < 1072; i += 256)
        ((float4*)sW)[i] = ((const float4*)W2)[i];
    __syncthreads();

    // ---- phase 2: c = tanh([x, r*s] @ W2 + b2); h = u*s + (1-u)*c ----
    int j4b = (tid & 15) * 4;
    int g2  = tid >> 4;
    float a2[2][4];
    #pragma unroll
    for (int i = 0; i < 2; i++)
        #pragma unroll
        for (int c = 0; c < 4; c++) a2[i][c] = sb2[j4b + c];

    #pragma unroll
    for (int f = 0; f < 3; f++) {
        float4 wv = *(float4*)&sW[f * 64 + j4b];
        #pragma unroll
        for (int i = 0; i < 2; i++) {
            float z = sz[g2 * 2 + i][64 + f];
            a2[i][0] += z * wv.x; a2[i][1] += z * wv.y;
            a2[i][2] += z * wv.z; a2[i][3] += z * wv.w;
        }
    }
    #pragma unroll 4
    for (int k = 0; k < 64; k++) {
        float4 wv = *(float4*)&sW[(3 + k) * 64 + j4b];
        #pragma unroll
        for (int i = 0; i < 2; i++) {
            float z = srs[(g2 * 2 + i) * 64 + k];
            a2[i][0] += z * wv.x; a2[i][1] += z * wv.y;
            a2[i][2] += z * wv.z; a2[i][3] += z * wv.w;
        }
    }

    float hh[2][4];
    #pragma unroll
    for (int i = 0; i < 2; i++) {
        int n = g2 * 2 + i;
        #pragma unroll
        for (int c = 0; c < 4; c++) {
            float cc = tanhf(a2[i][c]);
            float u = su[n * 64 + j4b + c];
            float s = sz[n][j4b + c];
            hh[i][c] = u * s + (1.0f - u) * cc;
        }
    }

    if (!last) {
        #pragma unroll
        for (int i = 0; i < 2; i++) {
            int nid = nbase + g2 * 2 + i;
            ((float4*)g_h)[nid * 16 + (j4b >> 2)] =
                make_float4(hh[i][0], hh[i][1], hh[i][2], hh[i][3]);
        }
    } else {
        __syncthreads();   // all reads of sz(s) done before overwrite with h
        #pragma unroll
        for (int i = 0; i < 2; i++)
            #pragma unroll
            for (int c = 0; c < 4; c++) sz[g2 * 2 + i][j4b + c] = hh[i][c];
        __syncthreads();
        if (tid < 96) {
            int ln = tid / 3, d = tid % 3;
            float acc3 = sob[d];
            #pragma unroll 8
            for (int k = 0; k < 64; k++) acc3 += sz[ln][k] * sow[k * 3 + d];
            out[(nbase + ln) * 3 + d] = acc3;
        }
    }
}

// ---------------- launch ----------------
extern "C" void kernel_launch(void* const* d_in, const int* in_sizes, int n_in,
                              void* d_out, int out_size)
{
    const float* x       = (const float*)d_in[0];
    const int*   src     = (const int*)  d_in[1];
    const int*   dst     = (const int*)  d_in[2];
    const float* gat_W   = (const float*)d_in[3];
    const float* a_src   = (const float*)d_in[4];
    const float* a_dst   = (const float*)d_in[5];
    const float* gat_b   = (const float*)d_in[6];
    const float* gru1_W  = (const float*)d_in[7];
    const float* gru1_b  = (const float*)d_in[8];
    const float* gru2_W  = (const float*)d_in[9];
    const float* gru2_b  = (const float*)d_in[10];
    const float* out_W   = (const float*)d_in[11];
    const float* out_b   = (const float*)d_in[12];
    float* out = (float*)d_out;

    gat0_count_kernel<<<4096 + 272, 256>>>(x, gat_W, a_src, a_dst, dst);
    scan_kernel<<<1, 1024>>>();
    scatter_kernel<<<(EF + 255) / 256, 256>>>(src, dst);

    for (int t = 0; t < TT; t++) {
        gat_gather_kernel<<<NN / 8, 256>>>(gat_b);
        gru_kernel<<<BN / 32, 256>>>(x, gru1_W, gru1_b, gru2_W, gru2_b,
                                     out_W, out_b, out, t, (t == TT - 1) ? 1 : 0);
        if (t < TT - 1)
            gat_node_kernel<<<BN / 64, 256>>>(x, gat_W, a_src, a_dst, t + 1);
    }
}